// round 16
// baseline (speedup 1.0000x reference)
#include <cuda_runtime.h>
#include <cuda_fp16.h>
#include <cstdint>
#include <cstddef>

#define BB 128
#define TT 1000
#define II 64
#define HH 512
#define ALPHA 0.2f

#define CLUSTER 8
#define H_TILE 64       // h rows per CTA
#define NTHR 256        // 8 warps: warp = (M-tile wid&3, K-half wid>>2)
#define KQ 36           // 576/16 k-steps (32 r + 4 x)
#define KH 18           // kq slots per warp
#define RCNT 2304       // u32 per buffer: 36*8*4*2
#define TX_BYTES 7168   // 7 peers * 256 threads * 4 B per step

// decision partials: [t][b][rank*8+wid] summed by dec_reduce (fixed order)
__device__ float g_decpart[TT * BB * 64];

// rbuf u32 layout: idx(kq, n, m, j) = ((kq*8 + n)*4 + m)*2 + j
// u32(kq,n,m,j) = halves (k = 16kq + 8j + 2m, +1), column b = n.
// MMA B-frag read: lane-linear conflict-free LDS.64 per kq.
__device__ __forceinline__ int ridx(int kq, int n, int m, int j) {
    return ((kq * 8 + n) * 4 + m) * 2 + j;
}

static __device__ __forceinline__ uint32_t s2u(const void* p) {
    return (uint32_t)__cvta_generic_to_shared(p);
}
static __device__ __forceinline__ uint32_t h2_as_u32(half2 h) {
    uint32_t u; __builtin_memcpy(&u, &h, 4); return u;
}
// remote u32 store with transaction completion on the peer's mbarrier
static __device__ __forceinline__ void st_async_u32(uint32_t addr, uint32_t mbar,
                                                    uint32_t rank, uint32_t v) {
    uint32_t ra, rm;
    asm volatile("mapa.shared::cluster.u32 %0, %1, %2;" : "=r"(ra) : "r"(addr), "r"(rank));
    asm volatile("mapa.shared::cluster.u32 %0, %1, %2;" : "=r"(rm) : "r"(mbar), "r"(rank));
    asm volatile("st.async.shared::cluster.mbarrier::complete_tx::bytes.u32 [%0], %1, [%2];"
                 :: "r"(ra), "r"(v), "r"(rm) : "memory");
}
static __device__ __forceinline__ void mbar_init(uint32_t addr, uint32_t cnt) {
    asm volatile("mbarrier.init.shared.b64 [%0], %1;" :: "r"(addr), "r"(cnt) : "memory");
}
static __device__ __forceinline__ void mbar_arm_tx(uint32_t addr, uint32_t tx) {
    asm volatile("mbarrier.arrive.expect_tx.shared::cta.b64 _, [%0], %1;"
                 :: "r"(addr), "r"(tx) : "memory");
}
static __device__ __forceinline__ void mbar_wait_acq(uint32_t addr, uint32_t parity) {
    asm volatile(
        "{.reg .pred P;\nWL%=:\n\t"
        "mbarrier.try_wait.parity.acquire.cluster.shared::cta.b64 P, [%0], %1;\n\t"
        "@!P bra WL%=;\n}"
        :: "r"(addr), "r"(parity) : "memory");
}
static __device__ __forceinline__ void mma_f16(float c[4], const uint32_t a[4], uint32_t b0, uint32_t b1) {
    asm volatile(
        "mma.sync.aligned.m16n8k16.row.col.f32.f16.f16.f32 "
        "{%0,%1,%2,%3}, {%4,%5,%6,%7}, {%8,%9}, {%0,%1,%2,%3};"
        : "+f"(c[0]), "+f"(c[1]), "+f"(c[2]), "+f"(c[3])
        : "r"(a[0]), "r"(a[1]), "r"(a[2]), "r"(a[3]), "r"(b0), "r"(b1));
}
static __device__ __forceinline__ float tanh_fast(float x) {
    float y; asm("tanh.approx.f32 %0, %1;" : "=f"(y) : "f"(x)); return y;
}

// grid = 128 CTAs in 16 clusters of 8. Cluster g: b rows [g*8, g*8+8).
// CTA rank r: h rows [r*64, +64). Per step per CTA:
// drive[64h, 8b] = W_cat[64h, 576k] . rcat[8b, 576k], fp16 HMMA fp32 acc
// -> 144 HMMA/CTA = 36/SMSP (half of cluster-4). Warp = (M-tile, K-half),
// 18 slots each; K-halves summed via staging. SLOT order: sg 0..3 own-rank
// r block, 4..7 x, 8..35 peers ring order (4 each). Half 0 = sg 0..17
// (local first -> pre-wait MMA), half 1 = sg 18..35 (all remote).
// Exchange: per-thread u32 st.async to 7 peers with complete_tx; monolithic
// two-parity tx barriers (R11 ledger). Decision partials fused.
__global__ void __launch_bounds__(NTHR, 1) __cluster_dims__(CLUSTER, 1, 1)
rnn_kernel(const float* __restrict__ x, const float* __restrict__ W_in,
           const float* __restrict__ b_in, const float* __restrict__ W_hh,
           const float* __restrict__ b_hh, const float* __restrict__ W_out,
           float* __restrict__ out_r)
{
    const int tid  = threadIdx.x;
    const int wid  = tid >> 5;
    const int lane = tid & 31;
    const int rank = blockIdx.x & (CLUSTER - 1);
    const int bg   = blockIdx.x >> 3;
    const int hbase = rank * H_TILE;
    const int b0g   = bg * 8;
    const int mt    = wid & 3;           // M-tile
    const int half  = wid >> 2;          // K half

    __shared__ __align__(16) uint32_t rbuf[2][RCNT];
    __shared__ __align__(16) float stg[2][H_TILE][12];
    __shared__ __align__(8) unsigned long long mbar[2];

    const uint32_t mb_a[2] = { s2u(&mbar[0]), s2u(&mbar[1]) };

    if (tid == 0) {
        mbar_init(mb_a[0], 1);
        mbar_init(mb_a[1], 1);
    }

    // zero buf0 (r(0) = 0; x region overwritten below)
    for (int i = tid; i < RCNT; i += NTHR) rbuf[0][i] = 0u;

    // ---- W fragments (A operand), slot order, packed fp16, once ----
    const int hA = hbase + mt * 16 + (lane >> 2);
    const int kA = 2 * (lane & 3);
    uint32_t a[KH][4];
    uint32_t soff[KH];                   // u32 offset of each slot's frag base
#pragma unroll
    for (int s = 0; s < KH; s++) {
        int sg = half * KH + s;
        int kq_phys;
        if (sg < 4)      kq_phys = rank * 4 + sg;
        else if (sg < 8) kq_phys = 32 + (sg - 4);
        else {
            int c = (sg - 8) >> 2, i = (sg - 8) & 3;
            kq_phys = (((rank + 1 + c) & 7) << 2) + i;
        }
        soff[s] = (uint32_t)(kq_phys * 64);
#pragma unroll
        for (int j = 0; j < 4; j++) {
            int h = hA + ((j & 1) ? 8 : 0);
            int k = kq_phys * 16 + kA + ((j & 2) ? 8 : 0);
            float2 w;
            if (k < HH) w = *(const float2*)&W_hh[h * HH + k];
            else        w = *(const float2*)&W_in[h * II + (k - HH)];
            a[s][j] = h2_as_u32(__floats2half2_rn(w.x, w.y));
        }
    }

    // ---- epilogue / writer mapping: thread -> (b = tid&7, h pair 2q) ----
    const int eb = tid & 7;
    const int q  = tid >> 3;             // 0..31
    const int hl = 2 * q;                // local h of first value
    const int ehg = hbase + hl;
    const int ebg = b0g + eb;
    const float bias0 = b_hh[ehg] + b_in[ehg];
    const float bias1 = b_hh[ehg + 1] + b_in[ehg + 1];
    const float wout0 = W_out[ehg], wout1 = W_out[ehg + 1];
    float r_old0 = 0.f, r_old1 = 0.f;
    // owned u32 slot: global k = rank*64 + hl
    const int sidx = ridx(rank * 4 + (q >> 3), eb, q & 3, (q >> 2) & 1);
    float* decslot = &g_decpart[(size_t)ebg * 64 + rank * 8 + wid];

    // ---- x staging mapping: one u32 per thread (256 threads = 256 u32) ----
    const int xj  = tid & 1;
    const int xm  = (tid >> 1) & 3;
    const int xkq = 32 + ((tid >> 3) & 3);
    const int xn  = tid >> 5;
    const int xi0 = (xkq - 32) * 16 + xj * 8 + 2 * xm;
    const float* xrow = &x[(size_t)(b0g + xn) * TT * II + xi0];
    const int xidx = ridx(xkq, xn, xm, xj);

    // stage x(0)
    {
        float2 xv = *(const float2*)&xrow[0];
        rbuf[0][xidx] = h2_as_u32(__floats2half2_rn(xv.x, xv.y));
    }
    __syncthreads();
    // arm both barriers BEFORE the cluster barrier so no peer store can
    // precede its expect_tx.
    if (tid == 0) {
        mbar_arm_tx(mb_a[0], TX_BYTES);
        mbar_arm_tx(mb_a[1], TX_BYTES);
    }
    asm volatile("barrier.cluster.arrive.aligned;" ::: "memory");
    asm volatile("barrier.cluster.wait.aligned;"   ::: "memory");

    int ph0 = 0, ph1 = 0;

#pragma unroll 1
    for (int t = 0; t < TT; t++) {
        const int p = t & 1;
        int tn = (t + 1 < TT) ? t + 1 : TT - 1;
        float2 xv = *(const float2*)&xrow[(size_t)tn * II];

        const uint32_t* rbp = &rbuf[p][lane * 2];

        float c[2][4];
#pragma unroll
        for (int cq = 0; cq < 2; cq++)
#pragma unroll
            for (int r = 0; r < 4; r++) c[cq][r] = 0.f;

        // ---- phase 1: half-0 warps run the 8 local slots (own r + x) ----
        if (half == 0) {
#pragma unroll
            for (int s = 0; s < 8; s++) {
                uint2 bv = *(const uint2*)&rbp[soff[s]];
                mma_f16(c[s & 1], a[s], bv.x, bv.y);
            }
        }

        // ---- wait for this step's remote data (tx barrier), then re-arm ----
        if (t > 0) {
            if (p) {
                mbar_wait_acq(mb_a[1], (uint32_t)ph1);
                if (tid == 0) mbar_arm_tx(mb_a[1], TX_BYTES);  // for step t+2
                ph1 ^= 1;
            } else {
                mbar_wait_acq(mb_a[0], (uint32_t)ph0);
                if (tid == 0) mbar_arm_tx(mb_a[0], TX_BYTES);  // for step t+2
                ph0 ^= 1;
            }
        }

        // ---- phase 2: remaining slots ----
        if (half == 0) {
#pragma unroll
            for (int s = 8; s < KH; s++) {
                uint2 bv = *(const uint2*)&rbp[soff[s]];
                mma_f16(c[s & 1], a[s], bv.x, bv.y);
            }
        } else {
#pragma unroll
            for (int s = 0; s < KH; s++) {
                uint2 bv = *(const uint2*)&rbp[soff[s]];
                mma_f16(c[s & 1], a[s], bv.x, bv.y);
            }
        }
        float cf[4];
#pragma unroll
        for (int r = 0; r < 4; r++) cf[r] = c[0][r] + c[1][r];

        // ---- stage partials: stg[half][h][b] ----
        {
            int rr = mt * 16 + (lane >> 2), cc = 2 * (lane & 3);
            *(float2*)&stg[half][rr][cc]     = make_float2(cf[0], cf[1]);
            *(float2*)&stg[half][rr + 8][cc] = make_float2(cf[2], cf[3]);
        }
        __syncthreads();

        // ---- epilogue: sum halves + tanh + leaky update (2 values) ----
        float s0 = stg[0][hl][eb]     + stg[1][hl][eb]     + bias0;
        float s1 = stg[0][hl + 1][eb] + stg[1][hl + 1][eb] + bias1;
        float rn0 = (1.0f - ALPHA) * r_old0 + ALPHA * tanh_fast(s0);
        float rn1 = (1.0f - ALPHA) * r_old1 + ALPHA * tanh_fast(s1);
        r_old0 = rn0; r_old1 = rn1;

        // ---- exchange: owned u32 -> 7 peers (st.async) + self ----
        uint32_t pv = h2_as_u32(__floats2half2_rn(rn0, rn1));
        uint32_t* dstb = rbuf[p ^ 1];
        dstb[sidx] = pv;                                   // self, generic STS
        const uint32_t daddr = s2u(&dstb[sidx]);
        const uint32_t mb_nxt = mb_a[p ^ 1];               // barrier for step t+1 data
#pragma unroll
        for (int cc = 1; cc < CLUSTER; cc++)
            st_async_u32(daddr, mb_nxt, (uint32_t)((rank + cc) & 7), pv);
        // stage x(t+1) (local region of next buffer)
        dstb[xidx] = h2_as_u32(__floats2half2_rn(xv.x, xv.y));

        // ---- post-send slack: out_r store + decision partial ----
        *(float2*)&out_r[((size_t)t * BB + ebg) * HH + ehg] = make_float2(rn0, rn1);
        {
            float pd = rn0 * wout0 + rn1 * wout1;
            pd += __shfl_down_sync(0xffffffffu, pd, 16);
            pd += __shfl_down_sync(0xffffffffu, pd, 8);
            if (lane < 8) decslot[(size_t)t * BB * 64] = pd;
        }

        // protects dstb (self/x STS) for next phase 1 and stg for next writes
        __syncthreads();
    }

    // terminal cluster sync: no CTA may exit while peers' st.async stores
    // targeting this CTA's SMEM/mbarriers can still be in flight.
    asm volatile("barrier.cluster.arrive.aligned;" ::: "memory");
    asm volatile("barrier.cluster.wait.aligned;"   ::: "memory");
}

// dec[i] = b_out + sum of 64 partials (fixed order -> deterministic)
__global__ void __launch_bounds__(256)
dec_reduce(const float* __restrict__ b_out, float* __restrict__ dec)
{
    int i = blockIdx.x * 256 + threadIdx.x;
    if (i >= TT * BB) return;
    const float4* s = (const float4*)&g_decpart[(size_t)i * 64];
    float sum = 0.f;
#pragma unroll
    for (int j = 0; j < 16; j++) {
        float4 v = s[j];
        sum += (v.x + v.y) + (v.z + v.w);
    }
    dec[i] = sum + b_out[0];
}

extern "C" void kernel_launch(void* const* d_in, const int* in_sizes, int n_in,
                              void* d_out, int out_size) {
    const float* x     = (const float*)d_in[0];
    const float* W_in  = (const float*)d_in[1];
    const float* b_in  = (const float*)d_in[2];
    const float* W_hh  = (const float*)d_in[3];
    const float* b_hh  = (const float*)d_in[4];
    const float* W_out = (const float*)d_in[5];
    const float* b_out = (const float*)d_in[6];

    float* dec   = (float*)d_out;                    // [T*B]
    float* out_r = (float*)d_out + (size_t)TT * BB;  // [T*B*H]

    rnn_kernel<<<BB, NTHR>>>(x, W_in, b_in, W_hh, b_hh, W_out, out_r);
    dec_reduce<<<(TT * BB + 255) / 256, 256>>>(b_out, dec);
}

// round 17
// speedup vs baseline: 1.5531x; 1.5531x over previous
#include <cuda_runtime.h>
#include <cuda_fp16.h>
#include <cstdint>
#include <cstddef>

#define BB 128
#define TT 1000
#define II 64
#define HH 512
#define ALPHA 0.2f

#define CLUSTER 8
#define H_TILE 64       // h rows per CTA
#define NTHR 256        // 8 warps: MMA warp = (M-tile wid&3, K-half wid>>2)
#define KQ 36           // 576/16 k-steps (32 r + 4 x)
#define KH 18           // kq slots per MMA warp
#define RCNT 2304       // u32 per buffer: 36*8*4*2
#define TX_BYTES 7168   // 7 peers * 256 threads * 4 B per step

// decision partials: [t][b][rank*4+kq_l] summed by dec_reduce (fixed order)
__device__ float g_decpart[TT * BB * 32];

// rbuf u32 layout: idx(kq, n, m, j) = ((kq*8 + n)*4 + m)*2 + j
// u32(kq,n,m,j) = halves (k = 16kq + 8j + 2m, +1), column b = n.
// MMA B-frag read: lane-linear conflict-free LDS.64 per kq.
// Exchange ownership (warp wid, lane): kq_l = wid>>1, idx = kq*64 +
// (wid&1)*32 + lane  -> warp's 32 u32 stores are CONTIGUOUS 128 B, so each
// st.async to a peer coalesces to ONE DSMEM transaction (R16's scattered
// 4-B stores -> 1792 transactions/step were the cluster-8 killer).
__device__ __forceinline__ int ridx(int kq, int n, int m, int j) {
    return ((kq * 8 + n) * 4 + m) * 2 + j;
}

static __device__ __forceinline__ uint32_t s2u(const void* p) {
    return (uint32_t)__cvta_generic_to_shared(p);
}
static __device__ __forceinline__ uint32_t h2_as_u32(half2 h) {
    uint32_t u; __builtin_memcpy(&u, &h, 4); return u;
}
static __device__ __forceinline__ uint32_t mapa_rank(uint32_t addr, uint32_t rank) {
    uint32_t r;
    asm volatile("mapa.shared::cluster.u32 %0, %1, %2;" : "=r"(r) : "r"(addr), "r"(rank));
    return r;
}
static __device__ __forceinline__ void st_async_u32_raw(uint32_t raddr, uint32_t rmbar, uint32_t v) {
    asm volatile("st.async.shared::cluster.mbarrier::complete_tx::bytes.u32 [%0], %1, [%2];"
                 :: "r"(raddr), "r"(v), "r"(rmbar) : "memory");
}
static __device__ __forceinline__ void mbar_init(uint32_t addr, uint32_t cnt) {
    asm volatile("mbarrier.init.shared.b64 [%0], %1;" :: "r"(addr), "r"(cnt) : "memory");
}
static __device__ __forceinline__ void mbar_arm_tx(uint32_t addr, uint32_t tx) {
    asm volatile("mbarrier.arrive.expect_tx.shared::cta.b64 _, [%0], %1;"
                 :: "r"(addr), "r"(tx) : "memory");
}
static __device__ __forceinline__ void mbar_wait_acq(uint32_t addr, uint32_t parity) {
    asm volatile(
        "{.reg .pred P;\nWL%=:\n\t"
        "mbarrier.try_wait.parity.acquire.cluster.shared::cta.b64 P, [%0], %1;\n\t"
        "@!P bra WL%=;\n}"
        :: "r"(addr), "r"(parity) : "memory");
}
static __device__ __forceinline__ void mma_f16(float c[4], const uint32_t a[4], uint32_t b0, uint32_t b1) {
    asm volatile(
        "mma.sync.aligned.m16n8k16.row.col.f32.f16.f16.f32 "
        "{%0,%1,%2,%3}, {%4,%5,%6,%7}, {%8,%9}, {%0,%1,%2,%3};"
        : "+f"(c[0]), "+f"(c[1]), "+f"(c[2]), "+f"(c[3])
        : "r"(a[0]), "r"(a[1]), "r"(a[2]), "r"(a[3]), "r"(b0), "r"(b1));
}
static __device__ __forceinline__ float tanh_fast(float x) {
    float y; asm("tanh.approx.f32 %0, %1;" : "=f"(y) : "f"(x)); return y;
}

// grid = 128 CTAs in 16 clusters of 8. Cluster g: b rows [g*8, g*8+8).
// CTA rank r: h rows [r*64, +64). 144 HMMA/CTA = 36/SMSP (rt16 -> ~576 cyc,
// half of cluster-4). MMA warp = (M-tile, K-half); K-halves summed via
// staging. SLOT order: sg 0..3 own-rank r, 4..7 x, 8..35 peers ring order.
// Exchange: coalesced per-warp u32 st.async to 7 peers with complete_tx;
// monolithic two-parity tx barriers (R11 ledger). Decision fused.
__global__ void __launch_bounds__(NTHR, 1) __cluster_dims__(CLUSTER, 1, 1)
rnn_kernel(const float* __restrict__ x, const float* __restrict__ W_in,
           const float* __restrict__ b_in, const float* __restrict__ W_hh,
           const float* __restrict__ b_hh, const float* __restrict__ W_out,
           float* __restrict__ out_r)
{
    const int tid  = threadIdx.x;
    const int wid  = tid >> 5;
    const int lane = tid & 31;
    const int rank = blockIdx.x & (CLUSTER - 1);
    const int bg   = blockIdx.x >> 3;
    const int hbase = rank * H_TILE;
    const int b0g   = bg * 8;
    const int mt    = wid & 3;           // MMA M-tile
    const int half  = wid >> 2;          // MMA K half

    __shared__ __align__(16) uint32_t rbuf[2][RCNT];
    __shared__ __align__(16) float stg[2][H_TILE][12];
    __shared__ __align__(8) unsigned long long mbar[2];

    const uint32_t mb_a[2] = { s2u(&mbar[0]), s2u(&mbar[1]) };

    if (tid == 0) {
        mbar_init(mb_a[0], 1);
        mbar_init(mb_a[1], 1);
    }

    // zero buf0 (r(0) = 0; x region overwritten below)
    for (int i = tid; i < RCNT; i += NTHR) rbuf[0][i] = 0u;

    // ---- W fragments (A operand), slot order, packed fp16, once ----
    const int hA = hbase + mt * 16 + (lane >> 2);
    const int kA = 2 * (lane & 3);
    uint32_t a[KH][4];
    uint32_t soff[KH];                   // u32 offset of each slot's frag base
#pragma unroll
    for (int s = 0; s < KH; s++) {
        int sg = half * KH + s;
        int kq_phys;
        if (sg < 4)      kq_phys = rank * 4 + sg;
        else if (sg < 8) kq_phys = 32 + (sg - 4);
        else {
            int c = (sg - 8) >> 2, i = (sg - 8) & 3;
            kq_phys = (((rank + 1 + c) & 7) << 2) + i;
        }
        soff[s] = (uint32_t)(kq_phys * 64);
#pragma unroll
        for (int j = 0; j < 4; j++) {
            int h = hA + ((j & 1) ? 8 : 0);
            int k = kq_phys * 16 + kA + ((j & 2) ? 8 : 0);
            float2 w;
            if (k < HH) w = *(const float2*)&W_hh[h * HH + k];
            else        w = *(const float2*)&W_in[h * II + (k - HH)];
            a[s][j] = h2_as_u32(__floats2half2_rn(w.x, w.y));
        }
    }

    // ---- exchange / epilogue mapping (lane-linear slot) ----
    const int kq_l  = wid >> 1;          // owned kq within rank block (0..3)
    const int nhalf = wid & 1;
    const int eb = nhalf * 4 + (lane >> 3);        // local b 0..7
    const int em = (lane >> 1) & 3;
    const int ej = lane & 1;
    const int hl = 16 * kq_l + 8 * ej + 2 * em;    // local h of first value
    const int ehg = hbase + hl;
    const int ebg = b0g + eb;
    const float bias0 = b_hh[ehg] + b_in[ehg];
    const float bias1 = b_hh[ehg + 1] + b_in[ehg + 1];
    const float wout0 = W_out[ehg], wout1 = W_out[ehg + 1];
    float r_old0 = 0.f, r_old1 = 0.f;
    const int sidx = (rank * 4 + kq_l) * 64 + nhalf * 32 + lane;  // lane-linear
    float* decslot = &g_decpart[(size_t)ebg * 32 + rank * 4 + kq_l];

    // ---- hoisted remote addresses (data slot + peer barrier, per buffer) ----
    uint32_t ra_r[2][7], rm_r[2][7];
#pragma unroll
    for (int bf = 0; bf < 2; bf++)
#pragma unroll
        for (int cc = 1; cc < CLUSTER; cc++) {
            uint32_t dstr = (uint32_t)((rank + cc) & 7);
            ra_r[bf][cc - 1] = mapa_rank(s2u(&rbuf[bf][sidx]), dstr);
            rm_r[bf][cc - 1] = mapa_rank(mb_a[bf], dstr);
        }

    // ---- x staging mapping: one u32 per thread (256 threads = 256 u32) ----
    const int xj  = tid & 1;
    const int xm  = (tid >> 1) & 3;
    const int xkq = 32 + ((tid >> 3) & 3);
    const int xn  = tid >> 5;
    const int xi0 = (xkq - 32) * 16 + xj * 8 + 2 * xm;
    const float* xrow = &x[(size_t)(b0g + xn) * TT * II + xi0];
    const int xidx = ridx(xkq, xn, xm, xj);

    // stage x(0)
    {
        float2 xv = *(const float2*)&xrow[0];
        rbuf[0][xidx] = h2_as_u32(__floats2half2_rn(xv.x, xv.y));
    }
    __syncthreads();
    // arm both barriers BEFORE the cluster barrier so no peer store can
    // precede its expect_tx.
    if (tid == 0) {
        mbar_arm_tx(mb_a[0], TX_BYTES);
        mbar_arm_tx(mb_a[1], TX_BYTES);
    }
    asm volatile("barrier.cluster.arrive.aligned;" ::: "memory");
    asm volatile("barrier.cluster.wait.aligned;"   ::: "memory");

    int ph0 = 0, ph1 = 0;

#pragma unroll 1
    for (int t = 0; t < TT; t++) {
        const int p = t & 1;
        int tn = (t + 1 < TT) ? t + 1 : TT - 1;
        float2 xv = *(const float2*)&xrow[(size_t)tn * II];

        const uint32_t* rbp = &rbuf[p][lane * 2];

        float c[2][4];
#pragma unroll
        for (int cq = 0; cq < 2; cq++)
#pragma unroll
            for (int r = 0; r < 4; r++) c[cq][r] = 0.f;

        // ---- phase 1: half-0 warps run the 8 local slots (own r + x) ----
        if (half == 0) {
#pragma unroll
            for (int s = 0; s < 8; s++) {
                uint2 bv = *(const uint2*)&rbp[soff[s]];
                mma_f16(c[s & 1], a[s], bv.x, bv.y);
            }
        }

        // ---- wait for this step's remote data (tx barrier), then re-arm ----
        if (t > 0) {
            if (p) {
                mbar_wait_acq(mb_a[1], (uint32_t)ph1);
                if (tid == 0) mbar_arm_tx(mb_a[1], TX_BYTES);  // for step t+2
                ph1 ^= 1;
            } else {
                mbar_wait_acq(mb_a[0], (uint32_t)ph0);
                if (tid == 0) mbar_arm_tx(mb_a[0], TX_BYTES);  // for step t+2
                ph0 ^= 1;
            }
        }

        // ---- phase 2: remaining slots ----
        if (half == 0) {
#pragma unroll
            for (int s = 8; s < KH; s++) {
                uint2 bv = *(const uint2*)&rbp[soff[s]];
                mma_f16(c[s & 1], a[s], bv.x, bv.y);
            }
        } else {
#pragma unroll
            for (int s = 0; s < KH; s++) {
                uint2 bv = *(const uint2*)&rbp[soff[s]];
                mma_f16(c[s & 1], a[s], bv.x, bv.y);
            }
        }
        float cf[4];
#pragma unroll
        for (int r = 0; r < 4; r++) cf[r] = c[0][r] + c[1][r];

        // ---- stage partials: stg[half][h][b] ----
        {
            int rr = mt * 16 + (lane >> 2), cc = 2 * (lane & 3);
            *(float2*)&stg[half][rr][cc]     = make_float2(cf[0], cf[1]);
            *(float2*)&stg[half][rr + 8][cc] = make_float2(cf[2], cf[3]);
        }
        __syncthreads();

        // ---- epilogue: sum halves + tanh + leaky update (2 values) ----
        float s0 = stg[0][hl][eb]     + stg[1][hl][eb]     + bias0;
        float s1 = stg[0][hl + 1][eb] + stg[1][hl + 1][eb] + bias1;
        float rn0 = (1.0f - ALPHA) * r_old0 + ALPHA * tanh_fast(s0);
        float rn1 = (1.0f - ALPHA) * r_old1 + ALPHA * tanh_fast(s1);
        r_old0 = rn0; r_old1 = rn1;

        // ---- exchange: owned u32 -> 7 peers (coalesced st.async) + self ----
        uint32_t pv = h2_as_u32(__floats2half2_rn(rn0, rn1));
        uint32_t* dstb = rbuf[p ^ 1];
        dstb[sidx] = pv;                                   // self, generic STS
        const int nb = p ^ 1;                              // buffer/parity of step t+1
#pragma unroll
        for (int cc = 0; cc < 7; cc++)
            st_async_u32_raw(ra_r[nb][cc], rm_r[nb][cc], pv);
        // stage x(t+1) (local region of next buffer)
        dstb[xidx] = h2_as_u32(__floats2half2_rn(xv.x, xv.y));

        // ---- post-send slack: out_r store + decision partial ----
        *(float2*)&out_r[((size_t)t * BB + ebg) * HH + ehg] = make_float2(rn0, rn1);
        {
            float pd = rn0 * wout0 + rn1 * wout1;
            pd += __shfl_down_sync(0xffffffffu, pd, 4);
            pd += __shfl_down_sync(0xffffffffu, pd, 2);
            pd += __shfl_down_sync(0xffffffffu, pd, 1);
            if ((lane & 7) == 0) decslot[(size_t)t * BB * 32] = pd;
        }

        // protects dstb (self/x STS) for next phase 1 and stg for next writes
        __syncthreads();
    }

    // terminal cluster sync: no CTA may exit while peers' st.async stores
    // targeting this CTA's SMEM/mbarriers can still be in flight.
    asm volatile("barrier.cluster.arrive.aligned;" ::: "memory");
    asm volatile("barrier.cluster.wait.aligned;"   ::: "memory");
}

// dec[i] = b_out + sum of 32 partials (fixed order -> deterministic)
__global__ void __launch_bounds__(256)
dec_reduce(const float* __restrict__ b_out, float* __restrict__ dec)
{
    int i = blockIdx.x * 256 + threadIdx.x;
    if (i >= TT * BB) return;
    const float4* s = (const float4*)&g_decpart[(size_t)i * 32];
    float sum = 0.f;
#pragma unroll
    for (int j = 0; j < 8; j++) {
        float4 v = s[j];
        sum += (v.x + v.y) + (v.z + v.w);
    }
    dec[i] = sum + b_out[0];
}

extern "C" void kernel_launch(void* const* d_in, const int* in_sizes, int n_in,
                              void* d_out, int out_size) {
    const float* x     = (const float*)d_in[0];
    const float* W_in  = (const float*)d_in[1];
    const float* b_in  = (const float*)d_in[2];
    const float* W_hh  = (const float*)d_in[3];
    const float* b_hh  = (const float*)d_in[4];
    const float* W_out = (const float*)d_in[5];
    const float* b_out = (const float*)d_in[6];

    float* dec   = (float*)d_out;                    // [T*B]
    float* out_r = (float*)d_out + (size_t)TT * BB;  // [T*B*H]

    rnn_kernel<<<BB, NTHR>>>(x, W_in, b_in, W_hh, b_hh, W_out, out_r);
    dec_reduce<<<(TT * BB + 255) / 256, 256>>>(b_out, dec);
}